// round 1
// baseline (speedup 1.0000x reference)
#include <cuda_runtime.h>
#include <math.h>

// ContextWindow: out[b, t, c*11 + i] = x[b, t+i-5, c] (zero pad in t),
// masked by t < round(2000 * lengths[b]).
// x: [32, 2000, 80] f32, lengths: [32] f32, out: [32, 2000, 880] f32.

#define B_    32
#define T_    2000
#define C_    80
#define CTX_  11          // LEFT(5) + RIGHT(5) + 1
#define TT_   32          // t-rows per block
#define SROWS (TT_ + 10)  // smem rows: tile + halo
#define SPAD  81          // padded smem row stride (bank-conflict break)
#define TB_   63          // ceil(2000 / 32) t-blocks per batch
#define J4_   (C_ * CTX_ / 4)  // 220 float4 per output row

__global__ __launch_bounds__(256) void context_window_kernel(
    const float* __restrict__ x,
    const float* __restrict__ lengths,
    float* __restrict__ out)
{
    __shared__ float s[SROWS * SPAD];

    const int blk = blockIdx.x;
    const int b   = blk / TB_;
    const int t0  = (blk % TB_) * TT_;

    // ---- Load tile + halo into smem (zero pad outside [0, T)) ----
    for (int idx = threadIdx.x; idx < SROWS * C_; idx += blockDim.x) {
        const int r = idx / C_;
        const int c = idx - r * C_;
        const int t = t0 + r - 5;
        float v = 0.0f;
        if (t >= 0 && t < T_)
            v = x[((size_t)b * T_ + t) * C_ + c];
        s[r * SPAD + c] = v;
    }

    // length mask threshold: jnp.round == round-half-to-even == rintf
    const int len_abs = (int)rintf((float)T_ * lengths[b]);

    __syncthreads();

    // ---- Emit coalesced float4 output ----
    float4* __restrict__ out4 = reinterpret_cast<float4*>(out);

    for (int q = threadIdx.x; q < TT_ * J4_; q += blockDim.x) {
        const int t_loc = q / J4_;
        const int t     = t0 + t_loc;
        if (t >= T_) continue;

        const float m = (t < len_abs) ? 1.0f : 0.0f;

        const unsigned j4 = (unsigned)(q - t_loc * J4_);
        const unsigned j  = j4 * 4u;
        unsigned c = j / CTX_;
        unsigned i = j - c * CTX_;

        float vals[4];
#pragma unroll
        for (int k = 0; k < 4; k++) {
            vals[k] = s[(t_loc + i) * SPAD + c] * m;
            i++;
            if (i == CTX_) { i = 0; c++; }
        }

        out4[((size_t)b * T_ + t) * J4_ + j4] =
            make_float4(vals[0], vals[1], vals[2], vals[3]);
    }
}

extern "C" void kernel_launch(void* const* d_in, const int* in_sizes, int n_in,
                              void* d_out, int out_size)
{
    const float* x       = (const float*)d_in[0];
    const float* lengths = (const float*)d_in[1];
    float* out           = (float*)d_out;

    (void)in_sizes; (void)n_in; (void)out_size;

    dim3 grid(B_ * TB_);   // 32 batches x 63 t-tiles = 2016 blocks
    dim3 block(256);
    context_window_kernel<<<grid, block>>>(x, lengths, out);
}

// round 2
// speedup vs baseline: 1.1382x; 1.1382x over previous
#include <cuda_runtime.h>
#include <math.h>

// ContextWindow: out[b, t, c*11 + i] = x[b, t+i-5, c] (zero pad in t),
// masked by t < round(2000 * lengths[b]).
// x: [32, 2000, 80] f32, lengths: [32] f32, out: [32, 2000, 880] f32.

#define B_    32
#define T_    2000
#define C_    80
#define CTX_  11          // LEFT(5) + RIGHT(5) + 1
#define TT_   32          // t-rows per block
#define SROWS (TT_ + 10)  // smem rows: tile + halo
#define SPAD  81          // padded smem row stride
#define TB_   63          // ceil(2000 / 32) t-blocks per batch
#define J4_   (C_ * CTX_ / 4)  // 220 float4 per output row
#define NTHR  224         // 220 active store threads + smem-fill helpers

__global__ __launch_bounds__(NTHR) void context_window_kernel(
    const float* __restrict__ x,
    const float* __restrict__ lengths,
    float* __restrict__ out)
{
    __shared__ float s[SROWS * SPAD];

    const int blk = blockIdx.x;
    const int b   = blk / TB_;
    const int t0  = (blk % TB_) * TT_;

    // jnp.round == round-half-to-even == rintf (RN)
    const int len_abs = (int)rintf((float)T_ * lengths[b]);
    const int n_stop  = min(TT_, T_ - t0);                    // rows that exist
    const int n_valid = min(max(len_abs - t0, 0), n_stop);    // rows that are non-zero

    // ---- Fill smem tile + halo (only if any row needs gathering) ----
    if (n_valid > 0) {
        for (int idx = threadIdx.x; idx < SROWS * C_; idx += NTHR) {
            const int r = idx / C_;
            const int c = idx - r * C_;
            const int t = t0 + r - 5;
            float v = 0.0f;
            if (t >= 0 && t < T_)
                v = x[((size_t)b * T_ + t) * C_ + c];
            s[r * SPAD + c] = v;
        }
    }
    __syncthreads();   // block-uniform condition above; barrier is uniform

    const int j4 = threadIdx.x;
    if (j4 >= J4_) return;

    // ---- Fixed per-thread mapping: j = 4*j4 covers (c,i) for k=0..3 ----
    const int j  = 4 * j4;
    int c0 = j / CTX_,  i0 = j - CTX_ * c0;
    int c1 = c0, i1 = i0 + 1; if (i1 == CTX_) { i1 = 0; c1++; }
    int c2 = c1, i2 = i1 + 1; if (i2 == CTX_) { i2 = 0; c2++; }
    int c3 = c2, i3 = i2 + 1; if (i3 == CTX_) { i3 = 0; c3++; }

    // boundary position: the k<3 with i_k == 10 (at most one); its column
    const bool bb0 = (i0 == CTX_ - 1);
    const bool bb1 = (i1 == CTX_ - 1);
    const bool bb2 = (i2 == CTX_ - 1);
    const bool anyb = bb0 | bb1 | bb2;
    const int  cb  = bb0 ? c0 : (bb1 ? c1 : c2);

    // ---- Prologue: load window for row t_loc = 0 ----
    float v0 = 0.f, v1 = 0.f, v2 = 0.f, v3 = 0.f;
    if (n_valid > 0) {
        v0 = s[i0 * SPAD + c0];
        v1 = s[i1 * SPAD + c1];
        v2 = s[i2 * SPAD + c2];
        v3 = s[i3 * SPAD + c3];
    }
    const float* q3 = &s[(1 + i3) * SPAD + c3];   // fresh value for vals[3]
    const float* qb = &s[(CTX_)   * SPAD + cb];   // fresh value at c-boundary (row 11)

    float4* outp = reinterpret_cast<float4*>(out)
                 + ((size_t)b * T_ + t0) * J4_ + j4;

    // ---- Valid rows: store + rotate register window (1-2 LDS per row) ----
#pragma unroll
    for (int tl = 0; tl < TT_; tl++) {
        if (tl >= n_valid) break;                 // block-uniform
        *outp = make_float4(v0, v1, v2, v3);
        outp += J4_;
        if (tl + 1 < n_valid) {                   // block-uniform
            float lb = 0.f;
            if (anyb) lb = *qb;                   // predicated per-thread LDS
            const float l3 = *q3;
            v0 = bb0 ? lb : v1;
            v1 = bb1 ? lb : v2;
            v2 = bb2 ? lb : v3;
            v3 = l3;
            q3 += SPAD;
            qb += SPAD;
        }
    }

    // ---- Masked tail rows: pure zero stores (DRAM-bound path) ----
    const float4 z = make_float4(0.f, 0.f, 0.f, 0.f);
    for (int tl = n_valid; tl < n_stop; tl++) {
        *outp = z;
        outp += J4_;
    }
}

extern "C" void kernel_launch(void* const* d_in, const int* in_sizes, int n_in,
                              void* d_out, int out_size)
{
    const float* x       = (const float*)d_in[0];
    const float* lengths = (const float*)d_in[1];
    float* out           = (float*)d_out;

    (void)in_sizes; (void)n_in; (void)out_size;

    dim3 grid(B_ * TB_);   // 32 batches x 63 t-tiles = 2016 blocks
    dim3 block(NTHR);
    context_window_kernel<<<grid, block>>>(x, lengths, out);
}

// round 3
// speedup vs baseline: 1.3647x; 1.1990x over previous
#include <cuda_runtime.h>
#include <math.h>

// ContextWindow: out[b, t, c*11 + i] = x[b, t+i-5, c] (zero pad in t),
// masked by t < round(2000 * lengths[b]).
// x: [32, 2000, 80] f32, lengths: [32] f32, out: [32, 2000, 880] f32.

#define B_    32
#define T_    2000
#define C_    80
#define CTX_  11
#define TT_   32          // t-rows per block
#define HALF_ 16          // rows per chain (2 chains per thread)
#define SROWS (TT_ + 10)  // 42 smem rows
#define SPAD  86          // bank key (22i + c) % 32: max 2-way conflict
#define TILES 63          // ceil(2000/32)
#define J4_   (C_ * CTX_ / 4)  // 220 float4 per output row
#define NTHR  224

__global__ __launch_bounds__(NTHR) void context_window_kernel(
    const float* __restrict__ x,
    const float* __restrict__ lengths,
    float* __restrict__ out)
{
    __shared__ float s[SROWS * SPAD];

    const int blk = blockIdx.x;
    const int b   = blk & 31;            // t-major: heavy (low t0) blocks first
    const int t0  = (blk >> 5) * TT_;

    // jnp.round == round-half-to-even == rintf
    const int len_abs = (int)rintf((float)T_ * lengths[b]);

    // chain A: rows [0,16) always exist (t0 <= 1984); chain B: rows [16,32)
    const int stopB = min(HALF_, T_ - t0 - HALF_);           // 0..16
    const int vA = min(max(len_abs - t0, 0), HALF_);
    const int vB = min(max(len_abs - t0 - HALF_, 0), max(stopB, 0));

    // ---- Fill smem tile + halo (only rows any gather will touch) ----
    if (vA > 0) {
        const int fill_rows = 10 + (vB > 0 ? HALF_ + vB : vA);   // <= 42
        for (int idx = threadIdx.x; idx < fill_rows * C_; idx += NTHR) {
            const int r = idx / C_;
            const int c = idx - r * C_;
            const int t = t0 + r - 5;
            float v = 0.0f;
            if (t >= 0 && t < T_)
                v = x[((size_t)b * T_ + t) * C_ + c];
            s[r * SPAD + c] = v;
        }
    }
    __syncthreads();   // guard condition is block-uniform

    const int j4 = threadIdx.x;
    if (j4 >= J4_) return;

    // ---- Fixed per-thread (c,i) mapping for j = 4*j4 .. 4*j4+3 ----
    const int j  = 4 * j4;
    int c0 = j / CTX_,  i0 = j - CTX_ * c0;
    int c1 = c0, i1 = i0 + 1; if (i1 == CTX_) { i1 = 0; c1++; }
    int c2 = c1, i2 = i1 + 1; if (i2 == CTX_) { i2 = 0; c2++; }
    int c3 = c2, i3 = i2 + 1; if (i3 == CTX_) { i3 = 0; c3++; }

    const bool bb0 = (i0 == CTX_ - 1);
    const bool bb1 = (i1 == CTX_ - 1);
    const bool bb2 = (i2 == CTX_ - 1);
    const bool anyb = bb0 | bb1 | bb2;
    const int  cb  = bb0 ? c0 : (bb1 ? c1 : c2);

    // ---- Prologues: independent windows for the two chains ----
    float a0 = 0.f, a1 = 0.f, a2 = 0.f, a3 = 0.f;
    float b0 = 0.f, b1 = 0.f, b2 = 0.f, b3 = 0.f;
    if (vA > 0) {
        a0 = s[i0 * SPAD + c0];
        a1 = s[i1 * SPAD + c1];
        a2 = s[i2 * SPAD + c2];
        a3 = s[i3 * SPAD + c3];
    }
    if (vB > 0) {
        b0 = s[(HALF_ + i0) * SPAD + c0];
        b1 = s[(HALF_ + i1) * SPAD + c1];
        b2 = s[(HALF_ + i2) * SPAD + c2];
        b3 = s[(HALF_ + i3) * SPAD + c3];
    }
    const float* q3A = &s[(1 + i3) * SPAD + c3];
    const float* qbA = &s[(CTX_)  * SPAD + cb];
    const float* q3B = q3A + HALF_ * SPAD;
    const float* qbB = qbA + HALF_ * SPAD;

    float4* outA = reinterpret_cast<float4*>(out)
                 + ((size_t)b * T_ + t0) * J4_ + j4;
    float4* outB = outA + (size_t)HALF_ * J4_;

    const float4 z = make_float4(0.f, 0.f, 0.f, 0.f);

#pragma unroll
    for (int tl = 0; tl < HALF_; tl++) {
        // chain A (rows always exist)
        if (tl < vA) {
            __stcs(outA, make_float4(a0, a1, a2, a3));
            if (tl + 1 < vA) {
                float lb = 0.f;
                if (anyb) lb = *qbA;
                const float l3 = *q3A;
                a0 = bb0 ? lb : a1;
                a1 = bb1 ? lb : a2;
                a2 = bb2 ? lb : a3;
                a3 = l3;
                q3A += SPAD; qbA += SPAD;
            }
        } else {
            __stcs(outA, z);
        }
        outA += J4_;

        // chain B
        if (tl < vB) {
            __stcs(outB, make_float4(b0, b1, b2, b3));
            if (tl + 1 < vB) {
                float lb = 0.f;
                if (anyb) lb = *qbB;
                const float l3 = *q3B;
                b0 = bb0 ? lb : b1;
                b1 = bb1 ? lb : b2;
                b2 = bb2 ? lb : b3;
                b3 = l3;
                q3B += SPAD; qbB += SPAD;
            }
        } else if (tl < stopB) {
            __stcs(outB, z);
        }
        outB += J4_;
    }
}

extern "C" void kernel_launch(void* const* d_in, const int* in_sizes, int n_in,
                              void* d_out, int out_size)
{
    const float* x       = (const float*)d_in[0];
    const float* lengths = (const float*)d_in[1];
    float* out           = (float*)d_out;

    (void)in_sizes; (void)n_in; (void)out_size;

    dim3 grid(TILES * B_);   // 63 t-tiles x 32 batches, t-major
    dim3 block(NTHR);
    context_window_kernel<<<grid, block>>>(x, lengths, out);
}

// round 4
// speedup vs baseline: 1.3873x; 1.0165x over previous
#include <cuda_runtime.h>
#include <math.h>

// ContextWindow: out[b, t, c*11 + i] = x[b, t+i-5, c] (zero pad in t),
// masked by t < round(2000 * lengths[b]).
// x: [32, 2000, 80] f32, lengths: [32] f32, out: [32, 2000, 880] f32.

#define B_    32
#define T_    2000
#define C_    80
#define CTX_  11
#define TT_   32              // t-rows per block
#define SROWS (TT_ + 10)      // 42 smem rows
#define SPAD  85              // bank key (5i + c) % 32: max 3-way, avg ~2
#define TILES 63              // ceil(2000/32)
#define J4_   (C_ * CTX_ / 4) // 220 float4 per output row
#define NTHR  224

__global__ __launch_bounds__(NTHR) void context_window_kernel(
    const float* __restrict__ x,
    const float* __restrict__ lengths,
    float* __restrict__ out)
{
    __shared__ float s[SROWS * SPAD];

    const int blk = blockIdx.x;
    const int b   = blk & 31;            // t-major: heavy (low t0) blocks first
    const int t0  = (blk >> 5) * TT_;

    // jnp.round == round-half-to-even == rintf
    const int len_abs = (int)rintf((float)T_ * lengths[b]);
    const int n_stop  = min(TT_, T_ - t0);                   // rows that exist
    const int v       = min(max(len_abs - t0, 0), n_stop);   // non-zero rows

    // ---- Fill smem tile + halo (only rows the gather will touch) ----
    if (v > 0) {
        const int fill_rows = v + 10;
        for (int idx = threadIdx.x; idx < fill_rows * C_; idx += NTHR) {
            const int r = idx / C_;
            const int c = idx - r * C_;
            const int t = t0 + r - 5;
            float val = 0.0f;
            if (t >= 0 && t < T_)
                val = x[((size_t)b * T_ + t) * C_ + c];
            s[r * SPAD + c] = val;
        }
    }
    __syncthreads();   // guard is block-uniform

    const int j4 = threadIdx.x;
    if (j4 >= J4_) return;

    // ---- Fixed per-thread (c,i) mapping for j = 4*j4 .. 4*j4+3 ----
    const int j  = 4 * j4;
    int c0 = j / CTX_,  i0 = j - CTX_ * c0;
    int c1 = c0, i1 = i0 + 1; if (i1 == CTX_) { i1 = 0; c1++; }
    int c2 = c1, i2 = i1 + 1; if (i2 == CTX_) { i2 = 0; c2++; }
    int c3 = c2, i3 = i2 + 1; if (i3 == CTX_) { i3 = 0; c3++; }

    const float* p0 = &s[i0 * SPAD + c0];
    const float* p1 = &s[i1 * SPAD + c1];
    const float* p2 = &s[i2 * SPAD + c2];
    const float* p3 = &s[i3 * SPAD + c3];

    float4* outp = reinterpret_cast<float4*>(out)
                 + ((size_t)b * T_ + t0) * J4_ + j4;

    int tl = 0;

    // ---- Valid rows, 4 at a time: 16 independent LDS, then 4 STG.128 ----
#pragma unroll 1
    for (; tl + 4 <= v; tl += 4) {
        float r[16];
#pragma unroll
        for (int u = 0; u < 4; u++) {
            const int o = (tl + u) * SPAD;
            r[4*u + 0] = p0[o];
            r[4*u + 1] = p1[o];
            r[4*u + 2] = p2[o];
            r[4*u + 3] = p3[o];
        }
#pragma unroll
        for (int u = 0; u < 4; u++)
            __stcs(outp + (size_t)u * J4_,
                   make_float4(r[4*u], r[4*u + 1], r[4*u + 2], r[4*u + 3]));
        outp += (size_t)4 * J4_;
    }

    // ---- Remaining valid rows ----
#pragma unroll 1
    for (; tl < v; tl++) {
        const int o = tl * SPAD;
        __stcs(outp, make_float4(p0[o], p1[o], p2[o], p3[o]));
        outp += J4_;
    }

    // ---- Masked tail rows: pure streaming zero stores ----
    const float4 z = make_float4(0.f, 0.f, 0.f, 0.f);
#pragma unroll 1
    for (; tl + 4 <= n_stop; tl += 4) {
#pragma unroll
        for (int u = 0; u < 4; u++)
            __stcs(outp + (size_t)u * J4_, z);
        outp += (size_t)4 * J4_;
    }
#pragma unroll 1
    for (; tl < n_stop; tl++) {
        __stcs(outp, z);
        outp += J4_;
    }
}

extern "C" void kernel_launch(void* const* d_in, const int* in_sizes, int n_in,
                              void* d_out, int out_size)
{
    const float* x       = (const float*)d_in[0];
    const float* lengths = (const float*)d_in[1];
    float* out           = (float*)d_out;

    (void)in_sizes; (void)n_in; (void)out_size;

    dim3 grid(TILES * B_);   // 63 t-tiles x 32 batches, t-major
    dim3 block(NTHR);
    context_window_kernel<<<grid, block>>>(x, lengths, out);
}